// round 1
// baseline (speedup 1.0000x reference)
#include <cuda_runtime.h>
#include <math.h>

#define B_  8192
#define H_  1024
#define HH_ 512
#define M_  16

// ---------------- scratch (device globals, no allocation) ----------------
__device__ float g_X1[B_ * HH_];     // gating hidden       [8192,512]
__device__ float g_Hbuf[B_ * HH_];   // expert hidden       [8192,512]
__device__ float g_Obuf[B_ * H_];    // expert output       [8192,1024]
__device__ int   g_top[B_];
__device__ int   g_rows[M_ * B_];
__device__ int   g_cnt[M_];

// ---------------- generic C[i,n] = act(sum_k A[i,k] * W[n,k] + b[n]) ------
// GROUPED: rows gathered per expert (blockIdx.z), weights offset per expert.
template<int RELU, int GROUPED>
__global__ __launch_bounds__(256, 2)
void gemm_tn(const float* __restrict__ A,
             const float* __restrict__ W,
             const float* __restrict__ bias,
             float* __restrict__ C,
             int N, int K, int plain_rows)
{
    constexpr int BM = 128, BN = 128, BK = 16;

    int nrows;
    const int*   rmap = nullptr;
    const float* Wp   = W;
    const float* bp   = bias;
    if (GROUPED) {
        int e = blockIdx.z;
        nrows = g_cnt[e];
        rmap  = &g_rows[e * B_];
        Wp    = W    + (size_t)e * N * K;
        bp    = bias + (size_t)e * N;
    } else {
        nrows = plain_rows;
    }

    int row0 = blockIdx.x * BM;
    if (row0 >= nrows) return;
    int col0 = blockIdx.y * BN;

    __shared__ float As[BK][BM + 4];
    __shared__ float Ws[BK][BN + 4];

    int t  = threadIdx.x;
    int lr = t >> 2;          // 0..63
    int lk = (t & 3) << 2;    // 0,4,8,12

    // A rows handled by this thread for loads: lr and lr+64
    int  ar0 = row0 + lr, ar1 = row0 + lr + 64;
    bool v0  = ar0 < nrows, v1 = ar1 < nrows;
    int  gr0 = v0 ? (GROUPED ? rmap[ar0] : ar0) : 0;
    int  gr1 = v1 ? (GROUPED ? rmap[ar1] : ar1) : 0;
    const float* Ap0 = A + (size_t)gr0 * K + lk;
    const float* Ap1 = A + (size_t)gr1 * K + lk;
    const float* Wq0 = Wp + (size_t)(col0 + lr)      * K + lk;
    const float* Wq1 = Wp + (size_t)(col0 + lr + 64) * K + lk;

    // prefetch chunk 0
    float4 pa0 = *(const float4*)Ap0;
    float4 pa1 = *(const float4*)Ap1;
    float4 pw0 = *(const float4*)Wq0;
    float4 pw1 = *(const float4*)Wq1;

    int tx = t & 15, ty = t >> 4;
    float acc[8][8];
#pragma unroll
    for (int i = 0; i < 8; i++)
#pragma unroll
        for (int j = 0; j < 8; j++) acc[i][j] = 0.0f;

    for (int k0 = 0; k0 < K; k0 += BK) {
        __syncthreads();
        As[lk + 0][lr]      = pa0.x; As[lk + 1][lr]      = pa0.y;
        As[lk + 2][lr]      = pa0.z; As[lk + 3][lr]      = pa0.w;
        As[lk + 0][lr + 64] = pa1.x; As[lk + 1][lr + 64] = pa1.y;
        As[lk + 2][lr + 64] = pa1.z; As[lk + 3][lr + 64] = pa1.w;
        Ws[lk + 0][lr]      = pw0.x; Ws[lk + 1][lr]      = pw0.y;
        Ws[lk + 2][lr]      = pw0.z; Ws[lk + 3][lr]      = pw0.w;
        Ws[lk + 0][lr + 64] = pw1.x; Ws[lk + 1][lr + 64] = pw1.y;
        Ws[lk + 2][lr + 64] = pw1.z; Ws[lk + 3][lr + 64] = pw1.w;
        __syncthreads();

        if (k0 + BK < K) {   // prefetch next chunk, overlapped with compute
            pa0 = *(const float4*)(Ap0 + k0 + BK);
            pa1 = *(const float4*)(Ap1 + k0 + BK);
            pw0 = *(const float4*)(Wq0 + k0 + BK);
            pw1 = *(const float4*)(Wq1 + k0 + BK);
        }

#pragma unroll
        for (int kk = 0; kk < BK; kk++) {
            float4 aA = *(const float4*)&As[kk][ty * 8];
            float4 aB = *(const float4*)&As[kk][ty * 8 + 4];
            float4 bA = *(const float4*)&Ws[kk][tx * 8];
            float4 bB = *(const float4*)&Ws[kk][tx * 8 + 4];
            float av[8] = {aA.x, aA.y, aA.z, aA.w, aB.x, aB.y, aB.z, aB.w};
            float bv[8] = {bA.x, bA.y, bA.z, bA.w, bB.x, bB.y, bB.z, bB.w};
#pragma unroll
            for (int i = 0; i < 8; i++)
#pragma unroll
                for (int j = 0; j < 8; j++)
                    acc[i][j] = fmaf(av[i], bv[j], acc[i][j]);
        }
    }

    // epilogue
#pragma unroll
    for (int i = 0; i < 8; i++) {
        int r = row0 + ty * 8 + i;
        if (r < nrows) {
            int gr = GROUPED ? rmap[r] : r;
            float* crow = C + (size_t)gr * N + col0 + tx * 8;
            float4 o0, o1;
            float bcol[8];
#pragma unroll
            for (int j = 0; j < 8; j++) bcol[j] = bp[col0 + tx * 8 + j];
            float v[8];
#pragma unroll
            for (int j = 0; j < 8; j++) {
                v[j] = acc[i][j] + bcol[j];
                if (RELU) v[j] = fmaxf(v[j], 0.0f);
            }
            o0.x = v[0]; o0.y = v[1]; o0.z = v[2]; o0.w = v[3];
            o1.x = v[4]; o1.y = v[5]; o1.z = v[6]; o1.w = v[7];
            *(float4*)(crow)     = o0;
            *(float4*)(crow + 4) = o1;
        }
    }
}

// --------- logits + argmax (softmax is monotone -> argmax of logits) ------
__global__ void logits_argmax_kernel(const float* __restrict__ W3,
                                     const float* __restrict__ b3)
{
    __shared__ float sW[M_ * HH_];
    __shared__ float sb[M_];
    for (int i = threadIdx.x; i < M_ * HH_; i += blockDim.x) sW[i] = W3[i];
    if (threadIdx.x < M_) sb[threadIdx.x] = b3[threadIdx.x];
    __syncthreads();

    int gw   = (blockIdx.x * blockDim.x + threadIdx.x) >> 5;
    int lane = threadIdx.x & 31;
    int nw   = (gridDim.x * blockDim.x) >> 5;

    for (int row = gw; row < B_; row += nw) {
        const float* x = g_X1 + (size_t)row * HH_;
        float xv[16];
#pragma unroll
        for (int tt = 0; tt < 16; tt++) xv[tt] = x[lane + 32 * tt];
        float best = -3.0e38f;
        int   bi   = 0;
#pragma unroll
        for (int m = 0; m < M_; m++) {
            float p = 0.0f;
            const float* wrow = sW + m * HH_;
#pragma unroll
            for (int tt = 0; tt < 16; tt++)
                p = fmaf(xv[tt], wrow[lane + 32 * tt], p);
#pragma unroll
            for (int o = 16; o; o >>= 1) p += __shfl_xor_sync(0xffffffffu, p, o);
            p += sb[m];
            if (p > best) { best = p; bi = m; }   // strict > == first-max (JAX tie rule)
        }
        if (lane == 0) g_top[row] = bi;
    }
}

// ---------------- bucket rows by expert ----------------
__global__ void zero_cnt_kernel() {
    if (threadIdx.x < M_) g_cnt[threadIdx.x] = 0;
}

__global__ void scatter_kernel() {
    int b = blockIdx.x * blockDim.x + threadIdx.x;
    if (b < B_) {
        int m = g_top[b];
        int p = atomicAdd(&g_cnt[m], 1);
        g_rows[m * B_ + p] = b;
    }
}

// ---------------- L2 normalize + residual ----------------
// normalize(g*v) == v / max(||v||,eps) for gate g>0 (top-1 softmax prob >= 1/16)
__global__ void finalize_kernel(const float* __restrict__ Q,
                                float* __restrict__ out)
{
    int row = blockIdx.x;
    const float* o = g_Obuf + (size_t)row * H_;
    float s = 0.0f;
#pragma unroll
    for (int i = threadIdx.x; i < H_; i += 256) { float v = o[i]; s = fmaf(v, v, s); }
#pragma unroll
    for (int off = 16; off; off >>= 1) s += __shfl_xor_sync(0xffffffffu, s, off);
    __shared__ float red[8];
    if ((threadIdx.x & 31) == 0) red[threadIdx.x >> 5] = s;
    __syncthreads();
    float tot = 0.0f;
#pragma unroll
    for (int w = 0; w < 8; w++) tot += red[w];
    float inv = 1.0f / fmaxf(sqrtf(tot), 1e-6f);

    const float* qr = Q + (size_t)row * H_;
    float* orow = out + (size_t)row * H_;
#pragma unroll
    for (int i = threadIdx.x; i < H_; i += 256)
        orow[i] = fmaf(o[i], inv, qr[i]);
}

// ---------------- launch ----------------
extern "C" void kernel_launch(void* const* d_in, const int* in_sizes, int n_in,
                              void* d_out, int out_size)
{
    const float* q   = (const float*)d_in[0];
    const float* c1w = (const float*)d_in[1];
    const float* c1b = (const float*)d_in[2];
    const float* c3w = (const float*)d_in[3];
    const float* c3b = (const float*)d_in[4];
    const float* ew1 = (const float*)d_in[5];
    const float* eb1 = (const float*)d_in[6];
    const float* ew2 = (const float*)d_in[7];
    const float* eb2 = (const float*)d_in[8];
    float* out = (float*)d_out;

    void *pX1, *pH, *pO;
    cudaGetSymbolAddress(&pX1, g_X1);
    cudaGetSymbolAddress(&pH,  g_Hbuf);
    cudaGetSymbolAddress(&pO,  g_Obuf);

    // 1) gating hidden: X1 = relu(Q @ cls1_w^T + b)   [8192,512], K=1024
    gemm_tn<1, 0><<<dim3(B_ / 128, HH_ / 128, 1), 256>>>(
        q, c1w, c1b, (float*)pX1, HH_, H_, B_);

    // 2) logits + argmax (softmax/gate value algebraically eliminated)
    logits_argmax_kernel<<<64, 256>>>(c3w, c3b);

    // 3) bucket rows by selected expert
    zero_cnt_kernel<<<1, 32>>>();
    scatter_kernel<<<B_ / 256, 256>>>();

    // 4) expert hidden: H = relu(Qg @ exp_w1[m]^T + b1[m])  per expert, K=1024
    gemm_tn<1, 1><<<dim3(B_ / 128, HH_ / 128, M_), 256>>>(
        q, ew1, eb1, (float*)pH, HH_, H_, 0);

    // 5) expert out: O = Hg @ exp_w2[m]^T + b2[m]            per expert, K=512
    gemm_tn<0, 1><<<dim3(B_ / 128, H_ / 128, M_), 256>>>(
        (const float*)pH, ew2, eb2, (float*)pO, H_, HH_, 0);

    // 6) out = normalize(O) + Q
    finalize_kernel<<<B_, 256>>>(q, out);
}

// round 3
// speedup vs baseline: 2.2227x; 2.2227x over previous
#include <cuda_runtime.h>
#include <cuda_bf16.h>
#include <cstdint>
#include <math.h>

#define B_  8192
#define H_  1024
#define HH_ 512
#define M_  16
#define BM  128
#define BN  128
#define NTH 256

typedef __nv_bfloat16 bf16;

// ---------------- scratch (device globals, no allocation) ----------------
__device__ bf16  g_qhi[B_ * H_];
__device__ bf16  g_qlo[B_ * H_];
__device__ bf16  g_w1hi[HH_ * H_];
__device__ bf16  g_w1lo[HH_ * H_];
__device__ bf16  g_ew1b[M_ * HH_ * H_];
__device__ bf16  g_ew2b[M_ * H_ * HH_];
__device__ float g_X1[B_ * HH_];
__device__ bf16  g_Hb[B_ * HH_];
__device__ float g_Obuf[B_ * H_];
__device__ int   g_top[B_];
__device__ int   g_rows[M_ * B_];
__device__ int   g_cnt[M_];

// ---------------- PTX helpers (all sm_80-compatible) ----------------
__device__ __forceinline__ uint32_t smem_u32(const void* p) {
    uint32_t a;
    asm("{ .reg .u64 t; cvta.to.shared.u64 t, %1; cvt.u32.u64 %0, t; }" : "=r"(a) : "l"(p));
    return a;
}
__device__ __forceinline__ void cp16(uint32_t dst, const void* src) {
    asm volatile("cp.async.cg.shared.global [%0], [%1], 16;" :: "r"(dst), "l"(src));
}
__device__ __forceinline__ void cp_commit() { asm volatile("cp.async.commit_group;" ::: "memory"); }
template <int N> __device__ __forceinline__ void cp_wait() {
    asm volatile("cp.async.wait_group %0;" :: "n"(N) : "memory");
}
__device__ __forceinline__ void ldmx4(uint32_t* r, uint32_t addr) {
    asm volatile("ldmatrix.sync.aligned.m8n8.x4.shared.b16 {%0,%1,%2,%3}, [%4];"
                 : "=r"(r[0]), "=r"(r[1]), "=r"(r[2]), "=r"(r[3]) : "r"(addr));
}
__device__ __forceinline__ void mma16816(float* d, const uint32_t* a, const uint32_t* b) {
    asm volatile(
        "mma.sync.aligned.m16n8k16.row.col.f32.bf16.bf16.f32 "
        "{%0,%1,%2,%3}, {%4,%5,%6,%7}, {%8,%9}, {%0,%1,%2,%3};"
        : "+f"(d[0]), "+f"(d[1]), "+f"(d[2]), "+f"(d[3])
        : "r"(a[0]), "r"(a[1]), "r"(a[2]), "r"(a[3]), "r"(b[0]), "r"(b[1]));
}

// ---------------- conversion kernels ----------------
__global__ void split_bf16_k(const float* __restrict__ x, bf16* __restrict__ hi,
                             bf16* __restrict__ lo, int n) {
    int i = (blockIdx.x * blockDim.x + threadIdx.x) * 4;
    if (i >= n) return;
    float4 v = *(const float4*)(x + i);
    bf16 h0 = __float2bfloat16_rn(v.x), h1 = __float2bfloat16_rn(v.y);
    bf16 h2 = __float2bfloat16_rn(v.z), h3 = __float2bfloat16_rn(v.w);
    bf16 l0 = __float2bfloat16_rn(v.x - __bfloat162float(h0));
    bf16 l1 = __float2bfloat16_rn(v.y - __bfloat162float(h1));
    bf16 l2 = __float2bfloat16_rn(v.z - __bfloat162float(h2));
    bf16 l3 = __float2bfloat16_rn(v.w - __bfloat162float(h3));
    *(__nv_bfloat162*)(hi + i)     = __nv_bfloat162(h0, h1);
    *(__nv_bfloat162*)(hi + i + 2) = __nv_bfloat162(h2, h3);
    *(__nv_bfloat162*)(lo + i)     = __nv_bfloat162(l0, l1);
    *(__nv_bfloat162*)(lo + i + 2) = __nv_bfloat162(l2, l3);
}

__global__ void cvt_bf16_k(const float* __restrict__ x, bf16* __restrict__ y, int n) {
    int i = (blockIdx.x * blockDim.x + threadIdx.x) * 4;
    if (i >= n) return;
    float4 v = *(const float4*)(x + i);
    *(__nv_bfloat162*)(y + i)     = __nv_bfloat162(__float2bfloat16_rn(v.x), __float2bfloat16_rn(v.y));
    *(__nv_bfloat162*)(y + i + 2) = __nv_bfloat162(__float2bfloat16_rn(v.z), __float2bfloat16_rn(v.w));
}

// ---------------- HMMA GEMM: C[i,n] = act(sum_k A[i,k]*W[n,k] + b[n]) ----
// SPLIT: 3-pass hi/lo bf16 (near-fp32). GROUPED: rows gathered via g_rows[e].
// Tiles: CTA 128x128xK64, 8 warps of 64x32, cp.async double buffer,
// xor-swizzled smem (row*128B, 16B unit swizzle), ldmatrix fragments.
template <int SPLIT, int GROUPED, int RELU, typename OutT>
__global__ __launch_bounds__(NTH)
void gemm_mma(const bf16* __restrict__ Ahi, const bf16* __restrict__ Alo,
              const bf16* __restrict__ Whi, const bf16* __restrict__ Wlo,
              const float* __restrict__ bias, OutT* __restrict__ C,
              int N, int K, int plain_rows)
{
    int e = GROUPED ? blockIdx.z : 0;
    int nrows = GROUPED ? g_cnt[e] : plain_rows;
    int row0 = blockIdx.x * BM;
    if (row0 >= nrows) return;
    int col0 = blockIdx.y * BN;

    const bf16*  Wh = Whi + (GROUPED ? (size_t)e * N * K : 0);
    const float* bp = bias + (GROUPED ? (size_t)e * N : 0);

    extern __shared__ char smem[];
    int*   srow  = (int*)smem;            // [128]
    float* sbias = (float*)(smem + 512);  // [128]
    constexpr int HDR   = 1024;
    constexpr int TILE  = BM * 128;       // 16KB per operand tile (128 rows x 128B)
    constexpr int STAGE = (1 + SPLIT) * 2 * TILE;
    constexpr int AHI = 0, ALO = TILE, WHI = (1 + SPLIT) * TILE, WLO = WHI + TILE;

    int t = threadIdx.x;
    if (t < BM) {
        int gr = row0 + t;
        srow[t] = GROUPED ? g_rows[e * B_ + (gr < nrows ? gr : nrows - 1)] : gr;
    }
    if (t < BN) sbias[t] = bp[col0 + t];
    __syncthreads();

    uint32_t sb = smem_u32(smem) + HDR;

    // loader: thread t -> row t>>1, 16B-chunks (t&1)*4 .. +3 (of 8 per 128B row)
    const int lrow = t >> 1, lhalf = (t & 1) * 4, lx7 = lrow & 7;
    const int nc = K >> 6;
    const size_t arow = (size_t)srow[lrow] * K;
    const size_t wrow = (size_t)(col0 + lrow) * K;

    auto issue = [&](int c) {
        uint32_t st = sb + (c & 1) * STAGE;
        size_t koff = (size_t)c * 64 + lhalf * 8;
#pragma unroll
        for (int j = 0; j < 4; j++) {
            uint32_t doff = lrow * 128 + (((lhalf + j) ^ lx7) * 16);
            cp16(st + AHI + doff, Ahi + arow + koff + j * 8);
            cp16(st + WHI + doff, Wh  + wrow + koff + j * 8);
            if (SPLIT) {
                cp16(st + ALO + doff, Alo + arow + koff + j * 8);
                cp16(st + WLO + doff, Wlo + wrow + koff + j * 8);
            }
        }
        cp_commit();
    };

    issue(0);
    issue(1);
    cp_wait<1>();
    __syncthreads();

    const int wid = t >> 5, lane = t & 31;
    const int wm = (wid & 1) * 64;   // warp row offset in tile
    const int wn = (wid >> 1) * 32;  // warp col offset in tile
    const int rb = lane & 15, csel = lane >> 4, x7 = rb & 7;

    float acc[4][4][4];
#pragma unroll
    for (int i = 0; i < 4; i++)
#pragma unroll
        for (int j = 0; j < 4; j++)
#pragma unroll
            for (int q = 0; q < 4; q++) acc[i][j][q] = 0.0f;

    // precomputed per-lane row byte offsets for ldmatrix
    uint32_t arow_b[4], wrow_b[2];
#pragma unroll
    for (int mi = 0; mi < 4; mi++) arow_b[mi] = (wm + mi * 16 + rb) * 128;
#pragma unroll
    for (int nb = 0; nb < 2; nb++) wrow_b[nb] = (wn + nb * 16 + rb) * 128;

    for (int c = 0; c < nc; c++) {
        uint32_t st = sb + (c & 1) * STAGE;
#pragma unroll
        for (int ks = 0; ks < 4; ks++) {
            uint32_t ksel = ((2 * ks + csel) ^ x7) * 16;
            uint32_t ah[4][4], bh[4][2];
#pragma unroll
            for (int mi = 0; mi < 4; mi++)
                ldmx4(ah[mi], st + AHI + arow_b[mi] + ksel);
#pragma unroll
            for (int nb = 0; nb < 2; nb++) {
                uint32_t r[4];
                ldmx4(r, st + WHI + wrow_b[nb] + ksel);
                bh[2 * nb][0] = r[0]; bh[2 * nb + 1][0] = r[1];
                bh[2 * nb][1] = r[2]; bh[2 * nb + 1][1] = r[3];
            }
#pragma unroll
            for (int mi = 0; mi < 4; mi++)
#pragma unroll
                for (int ni = 0; ni < 4; ni++)
                    mma16816(acc[mi][ni], ah[mi], bh[ni]);
            if (SPLIT) {
                uint32_t al[4][4], bl[4][2];
#pragma unroll
                for (int mi = 0; mi < 4; mi++)
                    ldmx4(al[mi], st + ALO + arow_b[mi] + ksel);
#pragma unroll
                for (int nb = 0; nb < 2; nb++) {
                    uint32_t r[4];
                    ldmx4(r, st + WLO + wrow_b[nb] + ksel);
                    bl[2 * nb][0] = r[0]; bl[2 * nb + 1][0] = r[1];
                    bl[2 * nb][1] = r[2]; bl[2 * nb + 1][1] = r[3];
                }
#pragma unroll
                for (int mi = 0; mi < 4; mi++)
#pragma unroll
                    for (int ni = 0; ni < 4; ni++) {
                        mma16816(acc[mi][ni], ah[mi], bl[ni]);
                        mma16816(acc[mi][ni], al[mi], bh[ni]);
                    }
            }
        }
        __syncthreads();               // all warps done reading stage (c&1)
        if (c + 2 < nc) issue(c + 2);
        else            cp_commit();   // keep group count uniform
        cp_wait<1>();
        __syncthreads();
    }

    // epilogue: acc[mi][ni] = {(r,c),(r,c+1),(r+8,c),(r+8,c+1)},
    // r = wm+mi*16+lane/4, c = wn+ni*8+2*(lane%3&3)
    const int lr4 = lane >> 2, lc2 = 2 * (lane & 3);
#pragma unroll
    for (int mi = 0; mi < 4; mi++) {
        int r0i = wm + mi * 16 + lr4;
        int r1i = r0i + 8;
        bool v0 = (row0 + r0i) < nrows;
        bool v1 = (row0 + r1i) < nrows;
        size_t g0 = (size_t)srow[r0i] * N + col0;
        size_t g1 = (size_t)srow[r1i] * N + col0;
#pragma unroll
        for (int ni = 0; ni < 4; ni++) {
            int cc = wn + ni * 8 + lc2;
            float ba = sbias[cc], bb = sbias[cc + 1];
            float x0 = acc[mi][ni][0] + ba, x1 = acc[mi][ni][1] + bb;
            float y0 = acc[mi][ni][2] + ba, y1 = acc[mi][ni][3] + bb;
            if (RELU) {
                x0 = fmaxf(x0, 0.0f); x1 = fmaxf(x1, 0.0f);
                y0 = fmaxf(y0, 0.0f); y1 = fmaxf(y1, 0.0f);
            }
            if (sizeof(OutT) == 4) {
                if (v0) *(float2*)((float*)C + g0 + cc) = make_float2(x0, x1);
                if (v1) *(float2*)((float*)C + g1 + cc) = make_float2(y0, y1);
            } else {
                uint32_t p0, p1;
                asm("cvt.rn.bf16x2.f32 %0, %1, %2;" : "=r"(p0) : "f"(x1), "f"(x0));
                asm("cvt.rn.bf16x2.f32 %0, %1, %2;" : "=r"(p1) : "f"(y1), "f"(y0));
                if (v0) *(uint32_t*)((bf16*)C + g0 + cc) = p0;
                if (v1) *(uint32_t*)((bf16*)C + g1 + cc) = p1;
            }
        }
    }
}

// --------- logits + argmax (softmax monotone -> argmax of logits) ------
__global__ void logits_argmax_kernel(const float* __restrict__ W3,
                                     const float* __restrict__ b3)
{
    __shared__ float sW[M_ * HH_];
    __shared__ float sb[M_];
    for (int i = threadIdx.x; i < M_ * HH_; i += blockDim.x) sW[i] = W3[i];
    if (threadIdx.x < M_) sb[threadIdx.x] = b3[threadIdx.x];
    __syncthreads();

    int gw   = (blockIdx.x * blockDim.x + threadIdx.x) >> 5;
    int lane = threadIdx.x & 31;
    int nw   = (gridDim.x * blockDim.x) >> 5;

    for (int row = gw; row < B_; row += nw) {
        const float* x = g_X1 + (size_t)row * HH_;
        float xv[16];
#pragma unroll
        for (int tt = 0; tt < 16; tt++) xv[tt] = x[lane + 32 * tt];
        float best = -3.0e38f;
        int   bi   = 0;
#pragma unroll
        for (int m = 0; m < M_; m++) {
            float p = 0.0f;
            const float* wrow = sW + m * HH_;
#pragma unroll
            for (int tt = 0; tt < 16; tt++)
                p = fmaf(xv[tt], wrow[lane + 32 * tt], p);
#pragma unroll
            for (int o = 16; o; o >>= 1) p += __shfl_xor_sync(0xffffffffu, p, o);
            p += sb[m];
            if (p > best) { best = p; bi = m; }   // strict > == first-max (JAX tie rule)
        }
        if (lane == 0) g_top[row] = bi;
    }
}

__global__ void zero_cnt_kernel() { if (threadIdx.x < M_) g_cnt[threadIdx.x] = 0; }

__global__ void scatter_kernel() {
    int b = blockIdx.x * blockDim.x + threadIdx.x;
    if (b < B_) {
        int m = g_top[b];
        int p = atomicAdd(&g_cnt[m], 1);
        g_rows[m * B_ + p] = b;
    }
}

// normalize(g*v) == v / max(||v||,eps) for gate g > 0 (top-1 prob >= 1/16)
__global__ void finalize_kernel(const float* __restrict__ Q, float* __restrict__ out)
{
    int row = blockIdx.x;
    const float* o = g_Obuf + (size_t)row * H_;
    float s = 0.0f;
    for (int i = threadIdx.x; i < H_; i += 256) { float v = o[i]; s = fmaf(v, v, s); }
#pragma unroll
    for (int off = 16; off; off >>= 1) s += __shfl_xor_sync(0xffffffffu, s, off);
    __shared__ float red[8];
    if ((threadIdx.x & 31) == 0) red[threadIdx.x >> 5] = s;
    __syncthreads();
    float tot = 0.0f;
#pragma unroll
    for (int w = 0; w < 8; w++) tot += red[w];
    float inv = 1.0f / fmaxf(sqrtf(tot), 1e-6f);

    const float* qr = Q + (size_t)row * H_;
    float* orow = out + (size_t)row * H_;
    for (int i = threadIdx.x; i < H_; i += 256)
        orow[i] = fmaf(o[i], inv, qr[i]);
}

// ---------------- launch ----------------
extern "C" void kernel_launch(void* const* d_in, const int* in_sizes, int n_in,
                              void* d_out, int out_size)
{
    const float* q   = (const float*)d_in[0];
    const float* c1w = (const float*)d_in[1];
    const float* c1b = (const float*)d_in[2];
    const float* c3w = (const float*)d_in[3];
    const float* c3b = (const float*)d_in[4];
    const float* ew1 = (const float*)d_in[5];
    const float* eb1 = (const float*)d_in[6];
    const float* ew2 = (const float*)d_in[7];
    const float* eb2 = (const float*)d_in[8];
    float* out = (float*)d_out;

    void *pqh, *pql, *pw1h, *pw1l, *pe1, *pe2, *pX1, *pHb, *pO;
    cudaGetSymbolAddress(&pqh,  g_qhi);
    cudaGetSymbolAddress(&pql,  g_qlo);
    cudaGetSymbolAddress(&pw1h, g_w1hi);
    cudaGetSymbolAddress(&pw1l, g_w1lo);
    cudaGetSymbolAddress(&pe1,  g_ew1b);
    cudaGetSymbolAddress(&pe2,  g_ew2b);
    cudaGetSymbolAddress(&pX1,  g_X1);
    cudaGetSymbolAddress(&pHb,  g_Hb);
    cudaGetSymbolAddress(&pO,   g_Obuf);

    // conversions
    split_bf16_k<<<(B_ * H_ / 4 + 255) / 256, 256>>>(q, (bf16*)pqh, (bf16*)pql, B_ * H_);
    split_bf16_k<<<(HH_ * H_ / 4 + 255) / 256, 256>>>(c1w, (bf16*)pw1h, (bf16*)pw1l, HH_ * H_);
    cvt_bf16_k<<<(M_ * HH_ * H_ / 4 + 255) / 256, 256>>>(ew1, (bf16*)pe1, M_ * HH_ * H_);
    cvt_bf16_k<<<(M_ * H_ * HH_ / 4 + 255) / 256, 256>>>(ew2, (bf16*)pe2, M_ * H_ * HH_);

    constexpr int SMEM_SPLIT = 1024 + 2 * 4 * BM * 128;  // 132096
    constexpr int SMEM_STD   = 1024 + 2 * 2 * BM * 128;  // 66560

    cudaFuncSetAttribute(gemm_mma<1, 0, 1, float>,
                         cudaFuncAttributeMaxDynamicSharedMemorySize, SMEM_SPLIT);
    cudaFuncSetAttribute(gemm_mma<0, 1, 1, bf16>,
                         cudaFuncAttributeMaxDynamicSharedMemorySize, SMEM_STD);
    cudaFuncSetAttribute(gemm_mma<0, 1, 0, float>,
                         cudaFuncAttributeMaxDynamicSharedMemorySize, SMEM_STD);

    // 1) gating hidden (split bf16 ~ fp32): X1 = relu(Q @ c1w^T + b)
    gemm_mma<1, 0, 1, float><<<dim3(B_ / BM, HH_ / BN, 1), NTH, SMEM_SPLIT>>>(
        (const bf16*)pqh, (const bf16*)pql, (const bf16*)pw1h, (const bf16*)pw1l,
        c1b, (float*)pX1, HH_, H_, B_);

    // 2) logits + argmax
    logits_argmax_kernel<<<64, 256>>>(c3w, c3b);

    // 3) bucket rows by expert
    zero_cnt_kernel<<<1, 32>>>();
    scatter_kernel<<<B_ / 256, 256>>>();

    // 4) expert hidden: H = relu(Qg @ ew1[m]^T + b1[m])  (bf16 out)
    gemm_mma<0, 1, 1, bf16><<<dim3(B_ / BM, HH_ / BN, M_), NTH, SMEM_STD>>>(
        (const bf16*)pqh, nullptr, (const bf16*)pe1, nullptr,
        eb1, (bf16*)pHb, HH_, H_, 0);

    // 5) expert out: O = Hg @ ew2[m]^T + b2[m]  (fp32 out)
    gemm_mma<0, 1, 0, float><<<dim3(B_ / BM, H_ / BN, M_), NTH, SMEM_STD>>>(
        (const bf16*)pHb, nullptr, (const bf16*)pe2, nullptr,
        eb2, (float*)pO, H_, HH_, 0);

    // 6) out = normalize(O) + Q
    finalize_kernel<<<B_, 256>>>(q, out);
}